// round 9
// baseline (speedup 1.0000x reference)
#include <cuda_runtime.h>
#include <cstdint>

// Problem constants (match reference_code)
#define N_ROWS 1000000
#define M_ROWS 2000000
#define DIM    128

// CSR-style row offsets: offsets[r] = lower_bound(sorted_indices, r).
// Segment for output row n = [offsets[n], offsets[n+1]).
// Every entry is written by build_offsets_kernel -> no zero-init needed.
__device__ int g_offsets[N_ROWS + 1];

// ---------------------------------------------------------------------------
// Kernel 1: build the full offsets array from the sorted int32 index array.
// Thread m (0..M inclusive):
//   m == 0      : offsets[r] = 0 for r in [0, idx[0]]
//   m == M      : offsets[r] = M for r in (idx[M-1], N]
//   else if idx[m] != idx[m-1]: offsets[r] = m for r in (idx[m-1], idx[m]]
// Each offsets entry is written exactly once.
// ---------------------------------------------------------------------------
__global__ void build_offsets_kernel(const int* __restrict__ idx) {
    int m = blockIdx.x * blockDim.x + threadIdx.x;
    if (m > M_ROWS) return;

    if (m == 0) {
        int first = idx[0];
        if (first < 0) first = 0;
        if (first > N_ROWS - 1) first = N_ROWS - 1;
        for (int r = 0; r <= first; ++r) g_offsets[r] = 0;
    } else if (m == M_ROWS) {
        int last = idx[M_ROWS - 1];
        if (last < 0) last = 0;
        if (last > N_ROWS - 1) last = N_ROWS - 1;
        for (int r = last + 1; r <= N_ROWS; ++r) g_offsets[r] = M_ROWS;
    } else {
        int cur  = idx[m];
        int prev = idx[m - 1];
        if (cur != prev) {
            if (prev < -1) prev = -1;               // defensive clamps
            if (cur > N_ROWS - 1) cur = N_ROWS - 1;
            for (int r = prev + 1; r <= cur; ++r) g_offsets[r] = m;
        }
    }
}

// ---------------------------------------------------------------------------
// Kernel 2: TWO consecutive rows per warp. Each lane owns one float4.
// Both var-row loads issue before the bounds-dependent value loads (deeper
// MLP at warp start); offsets contiguity means 3 scalar loads cover both
// rows (hi0 == lo1). The two segment loops are independent load streams.
// All big streams use-once: __ldcs / __stcs (evict-first).
// ---------------------------------------------------------------------------
__global__ void __launch_bounds__(256) gather_add_kernel(
    const float* __restrict__ var,
    const float* __restrict__ value,
    float* __restrict__ out)
{
    int warp_id = (blockIdx.x * blockDim.x + threadIdx.x) >> 5;
    int lane = threadIdx.x & 31;

    int r0 = warp_id * 2;
    if (r0 >= N_ROWS) return;
    int r1 = r0 + 1;                 // r1 < N_ROWS always (N_ROWS even)

    // Issue independent big loads first.
    float4 acc0 = __ldcs(&reinterpret_cast<const float4*>(var + (size_t)r0 * DIM)[lane]);
    float4 acc1 = __ldcs(&reinterpret_cast<const float4*>(var + (size_t)r1 * DIM)[lane]);

    // 3 bounds for 2 rows (contiguous CSR offsets); L2-resident.
    int lo0 = __ldg(&g_offsets[r0]);
    int mid = __ldg(&g_offsets[r1]);
    int hi1 = __ldg(&g_offsets[r1 + 1]);

    // Row 0 segment: [lo0, mid)
    {
        int m = lo0;
        for (; m + 1 < mid; m += 2) {
            float4 a = __ldcs(&reinterpret_cast<const float4*>(value + (size_t)m * DIM)[lane]);
            float4 b = __ldcs(&reinterpret_cast<const float4*>(value + (size_t)(m + 1) * DIM)[lane]);
            acc0.x += a.x + b.x;
            acc0.y += a.y + b.y;
            acc0.z += a.z + b.z;
            acc0.w += a.w + b.w;
        }
        if (m < mid) {
            float4 a = __ldcs(&reinterpret_cast<const float4*>(value + (size_t)m * DIM)[lane]);
            acc0.x += a.x; acc0.y += a.y; acc0.z += a.z; acc0.w += a.w;
        }
    }
    // Row 1 segment: [mid, hi1)
    {
        int m = mid;
        for (; m + 1 < hi1; m += 2) {
            float4 a = __ldcs(&reinterpret_cast<const float4*>(value + (size_t)m * DIM)[lane]);
            float4 b = __ldcs(&reinterpret_cast<const float4*>(value + (size_t)(m + 1) * DIM)[lane]);
            acc1.x += a.x + b.x;
            acc1.y += a.y + b.y;
            acc1.z += a.z + b.z;
            acc1.w += a.w + b.w;
        }
        if (m < hi1) {
            float4 a = __ldcs(&reinterpret_cast<const float4*>(value + (size_t)m * DIM)[lane]);
            acc1.x += a.x; acc1.y += a.y; acc1.z += a.z; acc1.w += a.w;
        }
    }

    __stcs(&reinterpret_cast<float4*>(out + (size_t)r0 * DIM)[lane], acc0);
    __stcs(&reinterpret_cast<float4*>(out + (size_t)r1 * DIM)[lane], acc1);
}

// ---------------------------------------------------------------------------
// Launch
// ---------------------------------------------------------------------------
extern "C" void kernel_launch(void* const* d_in, const int* in_sizes, int n_in,
                              void* d_out, int out_size) {
    const float* var   = (const float*)d_in[0];   // [N, 128] f32
    const float* value = (const float*)d_in[1];   // [M, 128] f32
    const int*   sidx  = (const int*)d_in[2];     // [M] i32 (JAX x64-off), sorted
    // d_in[3] = pos (unused)
    float* out = (float*)d_out;                   // [N, 128] f32

    {
        int threads = 256;
        int blocks = (M_ROWS + 1 + threads - 1) / threads;  // M+1 threads
        build_offsets_kernel<<<blocks, threads>>>(sidx);
    }
    {
        int threads = 256;                         // 8 warps = 16 rows per block
        int rows_per_block = (threads / 32) * 2;
        int blocks = (N_ROWS + rows_per_block - 1) / rows_per_block;
        gather_add_kernel<<<blocks, threads>>>(var, value, out);
    }
}

// round 11
// speedup vs baseline: 1.0252x; 1.0252x over previous
#include <cuda_runtime.h>
#include <cstdint>

// Problem constants (match reference_code)
#define N_ROWS 1000000
#define M_ROWS 2000000
#define DIM    128

// CSR-style row offsets: offsets[r] = lower_bound(sorted_indices, r).
// Segment for output row n = [offsets[n], offsets[n+1]).
// Every entry is written by build_offsets_kernel -> no zero-init needed.
__device__ int g_offsets[N_ROWS + 1];

// ---------------------------------------------------------------------------
// Kernel 1: build the full offsets array from the sorted int32 index array.
// Thread m (0..M inclusive):
//   m == 0      : offsets[r] = 0 for r in [0, idx[0]]
//   m == M      : offsets[r] = M for r in (idx[M-1], N]
//   else if idx[m] != idx[m-1]: offsets[r] = m for r in (idx[m-1], idx[m]]
// Each offsets entry is written exactly once.
// ---------------------------------------------------------------------------
__global__ void build_offsets_kernel(const int* __restrict__ idx) {
    int m = blockIdx.x * blockDim.x + threadIdx.x;
    if (m > M_ROWS) return;

    if (m == 0) {
        int first = idx[0];
        if (first < 0) first = 0;
        if (first > N_ROWS - 1) first = N_ROWS - 1;
        for (int r = 0; r <= first; ++r) g_offsets[r] = 0;
    } else if (m == M_ROWS) {
        int last = idx[M_ROWS - 1];
        if (last < 0) last = 0;
        if (last > N_ROWS - 1) last = N_ROWS - 1;
        for (int r = last + 1; r <= N_ROWS; ++r) g_offsets[r] = M_ROWS;
    } else {
        int cur  = idx[m];
        int prev = idx[m - 1];
        if (cur != prev) {
            if (prev < -1) prev = -1;               // defensive clamps
            if (cur > N_ROWS - 1) cur = N_ROWS - 1;
            for (int r = prev + 1; r <= cur; ++r) g_offsets[r] = m;
        }
    }
}

// ---------------------------------------------------------------------------
// Kernel 2 (R8 winner, + PDL): one warp per output row, lane owns one float4.
// The var-row load is independent of the offsets array, so it issues BEFORE
// cudaGridDependencySynchronize(); offsets (written by build_offsets_kernel)
// are only read after the grid dependency resolves.
// All big streams use-once: __ldcs / __stcs (evict-first).
// ---------------------------------------------------------------------------
__global__ void __launch_bounds__(256) gather_add_kernel(
    const float* __restrict__ var,
    const float* __restrict__ value,
    float* __restrict__ out)
{
    int warp_id = (blockIdx.x * blockDim.x + threadIdx.x) >> 5;
    if (warp_id >= N_ROWS) return;
    int lane = threadIdx.x & 31;

    // Independent of predecessor kernel: issue now, overlap with its tail.
    const float4* vrow = reinterpret_cast<const float4*>(var + (size_t)warp_id * DIM);
    float4 acc = __ldcs(&vrow[lane]);

    // Wait for build_offsets_kernel to complete before touching offsets.
    cudaGridDependencySynchronize();

    int lo = __ldg(&g_offsets[warp_id]);
    int hi = __ldg(&g_offsets[warp_id + 1]);

    // Average segment length is M/N = 2; unroll by 2 to expose MLP.
    int m = lo;
    for (; m + 1 < hi; m += 2) {
        float4 a = __ldcs(&reinterpret_cast<const float4*>(value + (size_t)m * DIM)[lane]);
        float4 b = __ldcs(&reinterpret_cast<const float4*>(value + (size_t)(m + 1) * DIM)[lane]);
        acc.x += a.x + b.x;
        acc.y += a.y + b.y;
        acc.z += a.z + b.z;
        acc.w += a.w + b.w;
    }
    if (m < hi) {
        float4 a = __ldcs(&reinterpret_cast<const float4*>(value + (size_t)m * DIM)[lane]);
        acc.x += a.x;
        acc.y += a.y;
        acc.z += a.z;
        acc.w += a.w;
    }

    __stcs(&reinterpret_cast<float4*>(out + (size_t)warp_id * DIM)[lane], acc);
}

// ---------------------------------------------------------------------------
// Launch: build_offsets normally; gather via cudaLaunchKernelEx with the
// programmatic-stream-serialization attribute (PDL). Graph-capturable.
// ---------------------------------------------------------------------------
extern "C" void kernel_launch(void* const* d_in, const int* in_sizes, int n_in,
                              void* d_out, int out_size) {
    const float* var   = (const float*)d_in[0];   // [N, 128] f32
    const float* value = (const float*)d_in[1];   // [M, 128] f32
    const int*   sidx  = (const int*)d_in[2];     // [M] i32 (JAX x64-off), sorted
    // d_in[3] = pos (unused)
    float* out = (float*)d_out;                   // [N, 128] f32

    {
        int threads = 256;
        int blocks = (M_ROWS + 1 + threads - 1) / threads;  // M+1 threads
        build_offsets_kernel<<<blocks, threads>>>(sidx);
    }
    {
        int threads = 256;                       // 8 warps per block
        int warps_per_block = threads / 32;
        int blocks = (N_ROWS + warps_per_block - 1) / warps_per_block;

        cudaLaunchConfig_t cfg = {};
        cfg.gridDim  = dim3((unsigned)blocks, 1, 1);
        cfg.blockDim = dim3((unsigned)threads, 1, 1);
        cfg.dynamicSmemBytes = 0;
        cfg.stream = 0;

        cudaLaunchAttribute attrs[1];
        attrs[0].id = cudaLaunchAttributeProgrammaticStreamSerialization;
        attrs[0].val.programmaticStreamSerializationAllowed = 1;
        cfg.attrs = attrs;
        cfg.numAttrs = 1;

        cudaLaunchKernelEx(&cfg, gather_add_kernel, var, value, out);
    }
}